// round 2
// baseline (speedup 1.0000x reference)
#include <cuda_runtime.h>
#include <cstdint>

// Problem constants
#define NUM_E 8
#define NUM_T 8192
#define NUM_K 2048
#define NUM_N 2048
#define NUM_G 16
#define PACKF 8

constexpr int BM = 128;
constexpr int BN = 128;
constexpr int BK = 32;
constexpr int THREADS = 256;

// ---------------- static device scratch (no allocations allowed) ----------------
__device__ int   g_counts[NUM_E];
__device__ int   g_offsets[NUM_E];
__device__ int   g_cursor[NUM_E];
__device__ int   g_sorted[NUM_T];
__device__ float g_bias[NUM_E * NUM_G * NUM_N];   // -zp * scale, 1 MB

// ---------------- prep kernels ----------------
__global__ void k_zero() {
    if (threadIdx.x < NUM_E) { g_counts[threadIdx.x] = 0; g_cursor[threadIdx.x] = 0; }
}

__global__ void k_count(const int* __restrict__ expert_ids) {
    int t = blockIdx.x * blockDim.x + threadIdx.x;
    if (t < NUM_T) atomicAdd(&g_counts[expert_ids[t]], 1);
}

__global__ void k_prefix() {
    if (threadIdx.x == 0) {
        int acc = 0;
        for (int e = 0; e < NUM_E; e++) { g_offsets[e] = acc; acc += g_counts[e]; }
    }
}

__global__ void k_scatter(const int* __restrict__ expert_ids) {
    int t = blockIdx.x * blockDim.x + threadIdx.x;
    if (t < NUM_T) {
        int e = expert_ids[t];
        int p = atomicAdd(&g_cursor[e], 1);
        g_sorted[g_offsets[e] + p] = t;
    }
}

__global__ void k_bias(const float* __restrict__ wscale, const int* __restrict__ zp) {
    int i = blockIdx.x * blockDim.x + threadIdx.x;
    if (i < NUM_E * NUM_G * NUM_N) g_bias[i] = -wscale[i] * (float)zp[i];
}

// ---------------- helpers ----------------
__device__ __forceinline__ unsigned f2tf32(float x) {
    unsigned r;
    asm("cvt.rna.tf32.f32 %0, %1;" : "=r"(r) : "f"(x));
    return r;
}

#define MMA_TF32(d, a, b)                                                      \
    asm volatile(                                                              \
        "mma.sync.aligned.m16n8k8.row.col.f32.tf32.tf32.f32 "                  \
        "{%0,%1,%2,%3}, {%4,%5,%6,%7}, {%8,%9}, {%0,%1,%2,%3};"                \
        : "+f"(d[0]), "+f"(d[1]), "+f"(d[2]), "+f"(d[3])                       \
        : "r"(a[0]), "r"(a[1]), "r"(a[2]), "r"(a[3]), "r"(b[0]), "r"(b[1]))

// ---------------- grouped GEMM ----------------
// grid: (N/BN, T/BM, E). Blocks whose m-tile exceeds this expert's token count exit.
__global__ __launch_bounds__(THREADS, 2)
void k_gemm(const float* __restrict__ state,       // [T, K]
            const int*   __restrict__ wpacked,     // [E, K/8, N]
            const float* __restrict__ wscale,      // [E, G, N]
            const int*   __restrict__ g_idx,       // [K]
            float*       __restrict__ out)         // [T, N]
{
    const int e     = blockIdx.z;
    const int cnt   = g_counts[e];
    const int mbase = blockIdx.y * BM;
    if (mbase >= cnt) return;
    const int off   = g_offsets[e];
    const int nbase = blockIdx.x * BN;

    __shared__ float As[BM][BK + 4];    // stride 36: conflict-free A-frag reads
    __shared__ float Bs[BK][BN + 8];    // stride 136: conflict-free B-frag reads
    __shared__ int   toks[BM];
    __shared__ int   gsh[BK];

    const int tid  = threadIdx.x;
    const int wid  = tid >> 5;
    const int lane = tid & 31;
    const int wm   = (wid >> 2) * 64;   // warp M offset (2 warp-rows)
    const int wn   = (wid & 3) * 32;    // warp N offset (4 warp-cols)
    const int grp  = lane >> 2;         // 0..7
    const int tig  = lane & 3;          // 0..3

    if (tid < BM) {
        int gm = mbase + tid;
        toks[tid] = (gm < cnt) ? g_sorted[off + gm] : g_sorted[off];  // clamp: dup row, never stored
    }

    float acc[4][4][4];
#pragma unroll
    for (int mi = 0; mi < 4; mi++)
#pragma unroll
        for (int ni = 0; ni < 4; ni++)
#pragma unroll
            for (int r = 0; r < 4; r++) acc[mi][ni][r] = 0.0f;

    const int*   wp_e = wpacked + (size_t)e * (NUM_K / PACKF) * NUM_N;
    const float* ws_e = wscale  + (size_t)e * NUM_G * NUM_N;
    const float* wb_e = g_bias  + (size_t)e * NUM_G * NUM_N;

    const int arow = tid >> 3;        // 0..31
    const int akq  = (tid & 7) * 4;   // 0,4,...,28

    __syncthreads();   // toks visible

    for (int k0 = 0; k0 < NUM_K; k0 += BK) {
        // ---- g_idx chunk ----
        if (tid < BK) gsh[tid] = g_idx[k0 + tid];

        // ---- A tile: gather 128 rows x 32 floats, convert to tf32 ----
#pragma unroll
        for (int p = 0; p < 4; p++) {
            int r = arow + p * 32;
            const float4 v = *reinterpret_cast<const float4*>(
                &state[(size_t)toks[r] * NUM_K + k0 + akq]);
            As[r][akq + 0] = __uint_as_float(f2tf32(v.x));
            As[r][akq + 1] = __uint_as_float(f2tf32(v.y));
            As[r][akq + 2] = __uint_as_float(f2tf32(v.z));
            As[r][akq + 3] = __uint_as_float(f2tf32(v.w));
        }
        __syncthreads();   // gsh visible for dequant below (and As half-barrier merged)

        // ---- B tile: dequant 4 packed rows x 128 cols -> 32 x 128 tf32 ----
        const int kp0 = k0 >> 3;   // k0 / 8
#pragma unroll
        for (int i = 0; i < 2; i++) {
            int w    = tid + i * THREADS;      // 0..511
            int prow = w >> 7;                 // 0..3
            int n    = w & 127;
            unsigned q32 = (unsigned)wp_e[(size_t)(kp0 + prow) * NUM_N + nbase + n];
#pragma unroll
            for (int j = 0; j < 8; j++) {
                int   kl = prow * 8 + j;
                int   g  = gsh[kl];
                float s  = ws_e[g * NUM_N + nbase + n];
                float b  = wb_e[g * NUM_N + nbase + n];
                float q  = (float)((q32 >> (4 * j)) & 15u);
                Bs[kl][n] = __uint_as_float(f2tf32(fmaf(q, s, b)));
            }
        }
        __syncthreads();

        // ---- MMA: 4 k8-steps ----
#pragma unroll
        for (int ks = 0; ks < BK; ks += 8) {
            unsigned af[4][4], bf[4][2];
#pragma unroll
            for (int mi = 0; mi < 4; mi++) {
                int mr = wm + mi * 16 + grp;
                af[mi][0] = __float_as_uint(As[mr    ][ks + tig    ]);
                af[mi][1] = __float_as_uint(As[mr + 8][ks + tig    ]);
                af[mi][2] = __float_as_uint(As[mr    ][ks + tig + 4]);
                af[mi][3] = __float_as_uint(As[mr + 8][ks + tig + 4]);
            }
#pragma unroll
            for (int ni = 0; ni < 4; ni++) {
                int nc = wn + ni * 8 + grp;
                bf[ni][0] = __float_as_uint(Bs[ks + tig    ][nc]);
                bf[ni][1] = __float_as_uint(Bs[ks + tig + 4][nc]);
            }
#pragma unroll
            for (int mi = 0; mi < 4; mi++)
#pragma unroll
                for (int ni = 0; ni < 4; ni++)
                    MMA_TF32(acc[mi][ni], af[mi], bf[ni]);
        }
        __syncthreads();   // guard smem overwrite next iteration
    }

    // ---- epilogue: scatter rows to out[token][n] ----
#pragma unroll
    for (int mi = 0; mi < 4; mi++) {
        int rl0 = wm + mi * 16 + grp;        // local row for c0/c1
        int rl1 = rl0 + 8;                   // local row for c2/c3
        bool v0 = (mbase + rl0) < cnt;
        bool v1 = (mbase + rl1) < cnt;
        int tok0 = toks[rl0];
        int tok1 = toks[rl1];
#pragma unroll
        for (int ni = 0; ni < 4; ni++) {
            int c = nbase + wn + ni * 8 + tig * 2;
            if (v0) {
                float2 val = make_float2(acc[mi][ni][0], acc[mi][ni][1]);
                *reinterpret_cast<float2*>(&out[(size_t)tok0 * NUM_N + c]) = val;
            }
            if (v1) {
                float2 val = make_float2(acc[mi][ni][2], acc[mi][ni][3]);
                *reinterpret_cast<float2*>(&out[(size_t)tok1 * NUM_N + c]) = val;
            }
        }
    }
}

// ---------------- launch ----------------
extern "C" void kernel_launch(void* const* d_in, const int* in_sizes, int n_in,
                              void* d_out, int out_size) {
    const float* state      = (const float*)d_in[0];
    const int*   wpacked    = (const int*)  d_in[1];
    const float* wscale     = (const float*)d_in[2];
    const int*   zp         = (const int*)  d_in[3];
    const int*   g_idx      = (const int*)  d_in[4];
    const int*   expert_ids = (const int*)  d_in[5];
    float*       out        = (float*)d_out;

    k_zero<<<1, 32>>>();
    k_count<<<NUM_T / 256, 256>>>(expert_ids);
    k_prefix<<<1, 32>>>();
    k_scatter<<<NUM_T / 256, 256>>>(expert_ids);
    k_bias<<<(NUM_E * NUM_G * NUM_N) / 256, 256>>>(wscale, zp);

    dim3 grid(NUM_N / BN, NUM_T / BM, NUM_E);
    k_gemm<<<grid, THREADS>>>(state, wpacked, wscale, g_idx, out);
}